// round 1
// baseline (speedup 1.0000x reference)
#include <cuda_runtime.h>
#include <math.h>

#define Bn 2
#define Ln 2048
#define Dn 512
#define Nn 4096
#define Gn 64
#define Tn 512
#define EPSN 1e-12f
#define EPSW 1e-8f

// ---------------- scratch (static device globals; no allocation) ----------------
__device__ __align__(256) float g_gn[Bn * Ln * Gn];   // unit group vectors, token storage
__device__ float g_norms[Bn * Ln];
__device__ float g_coef[Bn * Ln];                     // per-original-token x coefficient
__device__ int   g_lo[Bn * (Tn + 1)];                 // final slot range starts

// ---------------- K1: g = x @ w^T, norms, gn ----------------
// 64 threads (2 warps) per block, 4 tokens per block.
// Warp w handles group indices [w*32, w*32+32); lanes span D (coalesced w loads),
// x rows held in registers (4 tokens x 16 floats / lane).
__global__ void k_gn(const float* __restrict__ x, const float* __restrict__ w)
{
    int tok0 = blockIdx.x * 4;
    int warp = threadIdx.x >> 5;
    int lane = threadIdx.x & 31;

    float4 xr[4][4];
#pragma unroll
    for (int t = 0; t < 4; t++) {
        const float4* xp = (const float4*)(x + (size_t)(tok0 + t) * Dn);
#pragma unroll
        for (int q = 0; q < 4; q++) xr[t][q] = xp[lane + q * 32];
    }

    __shared__ float sg[4][Gn];
    __shared__ float snorm[4];

    for (int gg = 0; gg < 32; gg++) {
        int gi = warp * 32 + gg;
        const float4* wp = (const float4*)(w + (size_t)gi * Dn);
        float a0 = 0.f, a1 = 0.f, a2 = 0.f, a3 = 0.f;
#pragma unroll
        for (int q = 0; q < 4; q++) {
            float4 wv = wp[lane + q * 32];
            a0 += xr[0][q].x * wv.x + xr[0][q].y * wv.y + xr[0][q].z * wv.z + xr[0][q].w * wv.w;
            a1 += xr[1][q].x * wv.x + xr[1][q].y * wv.y + xr[1][q].z * wv.z + xr[1][q].w * wv.w;
            a2 += xr[2][q].x * wv.x + xr[2][q].y * wv.y + xr[2][q].z * wv.z + xr[2][q].w * wv.w;
            a3 += xr[3][q].x * wv.x + xr[3][q].y * wv.y + xr[3][q].z * wv.z + xr[3][q].w * wv.w;
        }
#pragma unroll
        for (int off = 16; off > 0; off >>= 1) {
            a0 += __shfl_down_sync(0xffffffffu, a0, off);
            a1 += __shfl_down_sync(0xffffffffu, a1, off);
            a2 += __shfl_down_sync(0xffffffffu, a2, off);
            a3 += __shfl_down_sync(0xffffffffu, a3, off);
        }
        if (lane == 0) { sg[0][gi] = a0; sg[1][gi] = a1; sg[2][gi] = a2; sg[3][gi] = a3; }
    }
    __syncthreads();

    if (threadIdx.x < 4) {
        int t = threadIdx.x;
        float ssum = 0.f;
        for (int gi = 0; gi < Gn; gi++) { float v = sg[t][gi]; ssum += v * v; }
        float nm = sqrtf(ssum);
        snorm[t] = nm;
        g_norms[tok0 + t] = nm;
    }
    __syncthreads();

    for (int idx = threadIdx.x; idx < 4 * Gn; idx += 64) {
        int t = idx >> 6, gi = idx & 63;
        g_gn[(size_t)(tok0 + t) * Gn + gi] = sg[t][gi] / fmaxf(snorm[t], EPSN);
    }
}

// ---------------- K2: merge plan simulation (1 block per batch) ----------------
// Key equivalence used (exact): the reference's capped greedy selection equals
// the first r_step members (in sim-descending, index-ascending order) of the
// UNCAPPED greedy maximal matching. The uncapped matching is computed by
// parallel priority-local-max fixed-point iteration; a bitonic sort is run only
// in rounds where the cap binds (|M| > r_step).
__global__ __launch_bounds__(1024) void k_merge()
{
    const int b = blockIdx.x;
    const int tid = threadIdx.x;
    const int NT = 1024;

    __shared__ float s_norm[Ln];
    __shared__ float s_sim[Ln];
    __shared__ unsigned short s_lo[Ln + 2];
    __shared__ unsigned char s_stat[Ln];      // 0 undecided, 1 accepted, 2 rejected, 3 selected
    __shared__ int s_scanA[Ln];
    __shared__ unsigned int s_skey[Ln];       // sort keys; reused as scan ping-pong buffer
    __shared__ unsigned short s_sidx[Ln];     // sort payload; reused as compaction temp
    __shared__ int sh_n, sh_rem, sh_m, sh_undec;

    float* gnb   = g_gn + (size_t)b * Ln * Gn;
    float* coefb = g_coef + b * Ln;

    for (int i = tid; i < Ln; i += NT) {
        s_norm[i] = g_norms[b * Ln + i];
        s_lo[i] = (unsigned short)i;
        coefb[i] = 1.0f;
    }
    if (tid == 0) { s_lo[Ln] = (unsigned short)Ln; sh_n = Ln; sh_rem = Ln - Tn; }
    __syncthreads();

    for (int round = 0; round < 24; round++) {
        int n = sh_n, rem = sh_rem;
        if (rem <= 0 || n < 2) break;

        // 1) adjacent sims from gn token storage
        for (int i = tid; i < n - 1; i += NT) {
            const float4* Ap = (const float4*)(gnb + (size_t)s_lo[i] * Gn);
            const float4* Bp = (const float4*)(gnb + (size_t)s_lo[i + 1] * Gn);
            float d = 0.f;
#pragma unroll
            for (int q = 0; q < 16; q++) {
                float4 a = Ap[q], c = Bp[q];
                d += a.x * c.x + a.y * c.y + a.z * c.z + a.w * c.w;
            }
            s_sim[i] = d;
            s_stat[i] = 0;
        }
        __syncthreads();

        // 2) uncapped greedy matching via local-max fixed point
        while (1) {
            if (tid == 0) sh_undec = 0;
            __syncthreads();
            for (int i = tid; i < n - 1; i += NT) {
                if (s_stat[i] == 0) {
                    float si = s_sim[i];
                    // priority: higher sim wins; tie -> lower index wins
                    bool hiL = (i > 0) && (s_sim[i - 1] >= si);
                    bool hiR = (i + 1 < n - 1) && (s_sim[i + 1] > si);
                    unsigned char a = hiL ? s_stat[i - 1] : (unsigned char)2;
                    unsigned char c = hiR ? s_stat[i + 1] : (unsigned char)2;
                    if (a == 2 && c == 2) s_stat[i] = 1;
                    else if (a == 1 || c == 1) s_stat[i] = 2;
                    else atomicAdd(&sh_undec, 1);
                }
            }
            __syncthreads();
            int u = sh_undec;
            __syncthreads();
            if (u == 0) break;
        }

        // 3) |M| count
        if (tid == 0) sh_m = 0;
        __syncthreads();
        {
            int lm = 0;
            for (int i = tid; i < n - 1; i += NT) lm += (s_stat[i] == 1);
#pragma unroll
            for (int off = 16; off > 0; off >>= 1) lm += __shfl_down_sync(0xffffffffu, lm, off);
            if ((tid & 31) == 0) atomicAdd(&sh_m, lm);
        }
        __syncthreads();
        int m = sh_m;
        int r_step = min(rem, n >> 1);
        int cnt = min(m, r_step);

        // 4) selection
        if (m > r_step) {
            // bitonic sort (descending) of accepted sims; others keyed 0 (minimum)
            for (int i = tid; i < Ln; i += NT) {
                unsigned int key = 0u;
                if (i < n - 1 && s_stat[i] == 1) {
                    unsigned int u = __float_as_uint(s_sim[i]);
                    key = (u & 0x80000000u) ? ~u : (u | 0x80000000u);
                }
                s_skey[i] = key;
                s_sidx[i] = (unsigned short)i;
            }
            __syncthreads();
            for (int k = 2; k <= Ln; k <<= 1) {
                for (int j = k >> 1; j > 0; j >>= 1) {
                    for (int i = tid; i < Ln; i += NT) {
                        int ixj = i ^ j;
                        if (ixj > i) {
                            unsigned int a = s_skey[i], c = s_skey[ixj];
                            bool dir = ((i & k) == 0);
                            bool sw = dir ? (a < c) : (a > c);
                            if (sw) {
                                s_skey[i] = c; s_skey[ixj] = a;
                                unsigned short t1 = s_sidx[i];
                                s_sidx[i] = s_sidx[ixj]; s_sidx[ixj] = t1;
                            }
                        }
                    }
                    __syncthreads();
                }
            }
            for (int r = tid; r < r_step; r += NT) s_stat[s_sidx[r]] = 3;
            __syncthreads();
        } else {
            for (int i = tid; i < n - 1; i += NT) if (s_stat[i] == 1) s_stat[i] = 3;
            __syncthreads();
        }

        // 5) apply merges (selected pairs are non-overlapping -> race-free)
        for (int i = tid; i < n - 1; i += NT) {
            if (s_stat[i] == 3) {
                float wi = s_norm[i], wj = s_norm[i + 1];
                float tot = wi + wj + EPSW;
                int ta = s_lo[i], tb = s_lo[i + 1], tc2 = s_lo[i + 2];
                float4* Ap = (float4*)(gnb + (size_t)ta * Gn);
                const float4* Bp = (const float4*)(gnb + (size_t)tb * Gn);
                float ssq = 0.f;
#pragma unroll
                for (int q = 0; q < 16; q++) {
                    float4 a = Ap[q], c = Bp[q];
                    float mx = (wi * a.x + wj * c.x) / tot;
                    float my = (wi * a.y + wj * c.y) / tot;
                    float mz = (wi * a.z + wj * c.z) / tot;
                    float mw = (wi * a.w + wj * c.w) / tot;
                    ssq += mx * mx + my * my + mz * mz + mw * mw;
                }
                float inv = 1.f / fmaxf(sqrtf(ssq), EPSN);
#pragma unroll
                for (int q = 0; q < 16; q++) {
                    float4 a = Ap[q], c = Bp[q];
                    float4 o;
                    o.x = (wi * a.x + wj * c.x) / tot * inv;
                    o.y = (wi * a.y + wj * c.y) / tot * inv;
                    o.z = (wi * a.z + wj * c.z) / tot * inv;
                    o.w = (wi * a.w + wj * c.w) / tot * inv;
                    Ap[q] = o;
                }
                float fa = wi / tot, fb = wj / tot;
                for (int t = ta; t < tb; t++) coefb[t] *= fa;
                for (int t = tb; t < tc2; t++) coefb[t] *= fb;
                s_norm[i] = (wi + wj) * 0.5f;
            }
        }
        __syncthreads();

        // 6) compaction of slot arrays (drop 'second' slots) via Hillis-Steele scan
        int* Aq = s_scanA;
        int* Bq = (int*)s_skey;
        for (int j = tid; j < n; j += NT)
            Aq[j] = (j > 0 && s_stat[j - 1] == 3) ? 0 : 1;
        __syncthreads();
        for (int off = 1; off < n; off <<= 1) {
            for (int j = tid; j < n; j += NT)
                Bq[j] = Aq[j] + ((j >= off) ? Aq[j - off] : 0);
            __syncthreads();
            int* tp = Aq; Aq = Bq; Bq = tp;
        }
        for (int j = tid; j < n; j += NT) {
            if (!(j > 0 && s_stat[j - 1] == 3)) {
                int p = Aq[j] - 1;
                s_sim[p] = s_norm[j];             // temp for norms
                s_sidx[p] = s_lo[j];              // temp for lo
            }
        }
        __syncthreads();
        int newn = n - cnt;
        for (int j = tid; j < newn; j += NT) { s_norm[j] = s_sim[j]; s_lo[j] = s_sidx[j]; }
        if (tid == 0) { s_lo[newn] = (unsigned short)Ln; sh_n = newn; sh_rem = rem - cnt; }
        __syncthreads();
    }

    for (int k = tid; k <= Tn; k += NT) g_lo[b * (Tn + 1) + k] = (int)s_lo[k];
}

// ---------------- K3: apply plan (bandwidth-bound) ----------------
// chunk 0 -> x_m (coef-weighted segment sum over D=512)
// chunks 1..8 -> s_m (plain segment sum over 512-float column chunks of N=4096)
__global__ void k_apply(const float* __restrict__ x, const float* __restrict__ s,
                        float* __restrict__ out)
{
    int kslot = blockIdx.x;
    int chunk = blockIdx.y;
    int b = blockIdx.z;
    int lo = g_lo[b * (Tn + 1) + kslot];
    int hi = g_lo[b * (Tn + 1) + kslot + 1];
    int t4 = threadIdx.x;  // 128 threads x float4 = 512 floats

    if (chunk == 0) {
        float4 acc = make_float4(0.f, 0.f, 0.f, 0.f);
        for (int t = lo; t < hi; t++) {
            float c = g_coef[b * Ln + t];
            float4 v = ((const float4*)(x + ((size_t)b * Ln + t) * Dn))[t4];
            acc.x += c * v.x; acc.y += c * v.y; acc.z += c * v.z; acc.w += c * v.w;
        }
        ((float4*)(out + ((size_t)b * Tn + kslot) * Dn))[t4] = acc;
    } else {
        int c0 = (chunk - 1) * 512;
        float4 acc = make_float4(0.f, 0.f, 0.f, 0.f);
        for (int t = lo; t < hi; t++) {
            float4 v = ((const float4*)(s + ((size_t)b * Ln + t) * Nn + c0))[t4];
            acc.x += v.x; acc.y += v.y; acc.z += v.z; acc.w += v.w;
        }
        ((float4*)(out + (size_t)Bn * Tn * Dn + ((size_t)b * Tn + kslot) * Nn + c0))[t4] = acc;
    }
}

// ---------------- launch ----------------
extern "C" void kernel_launch(void* const* d_in, const int* in_sizes, int n_in,
                              void* d_out, int out_size)
{
    const float* x = (const float*)d_in[0];
    const float* src = (const float*)d_in[1];
    const float* w = (const float*)d_in[2];
    float* out = (float*)d_out;

    k_gn<<<Bn * Ln / 4, 64>>>(x, w);
    k_merge<<<Bn, 1024>>>();
    dim3 g3(Tn, 1 + Nn / 512, Bn);
    k_apply<<<g3, 128>>>(x, src, out);
}